// round 5
// baseline (speedup 1.0000x reference)
#include <cuda_runtime.h>

// Inputs: q, r, Ek, Ev, Mk, Mv0, We, be, Wa, ba, Wf, bf, Wp, bp
// q,r int32 [64,512]; rest float32. Output: p [64,512] float32.

#define NUM_C 1000
#define DIM   128
#define MSZ   64
#define BB    64
#define LL    512
#define NTOK  (BB*LL)

typedef unsigned long long ull;

// ---------------- device scratch ----------------
__device__ float g_w  [NUM_C*MSZ];     // softmax(Ek[q] @ Mk^T)          [1000,64]
__device__ float g_ne [2*NUM_C*DIM];   // -sigmoid(Ev@We+be)  (negated!) [2000,128]
__device__ float g_a  [2*NUM_C*DIM];   // tanh(Ev@Wa+ba)                 [2000,128]
__device__ float g_fk [NUM_C*DIM];     // Ek@Wf[128:256] + bf            [1000,128]
__device__ float g_read[NTOK*DIM];     // scan output                    [B*L,128]

// ---------------- f32x2 helpers ----------------
__device__ __forceinline__ ull fma2(ull a, ull b, ull c) {
    ull d; asm("fma.rn.f32x2 %0, %1, %2, %3;" : "=l"(d) : "l"(a), "l"(b), "l"(c)); return d;
}
__device__ __forceinline__ ull add2(ull a, ull b) {
    ull d; asm("add.rn.f32x2 %0, %1, %2;" : "=l"(d) : "l"(a), "l"(b)); return d;
}
__device__ __forceinline__ ull pack2(float x, float y) {
    ull d; asm("mov.b64 %0, {%1, %2};" : "=l"(d) : "f"(x), "f"(y)); return d;
}
__device__ __forceinline__ float2 unpack2(ull v) {
    float2 r; asm("mov.b64 {%0, %1}, %2;" : "=f"(r.x), "=f"(r.y) : "l"(v)); return r;
}
__device__ __forceinline__ float sigmoid_fast(float x) {
    return __fdividef(1.0f, 1.0f + __expf(-x));
}
__device__ __forceinline__ float tanh_fast(float x) {
    return 1.0f - __fdividef(2.0f, __expf(2.0f * x) + 1.0f);
}

// ======================================================================
// Kernel 1a: softmax correlation-weight table. 50 blocks x 10 q-pairs.
// ======================================================================
#define WT_BLOCKS 50
#define WT_PAIRS  10

__global__ void __launch_bounds__(128) k_wtab(const float* __restrict__ Ek,
                                              const float* __restrict__ Mk) {
    __shared__ float mk[MSZ][DIM + 2];
    __shared__ float ek[2][2][DIM];
    __shared__ float xmax[2][4];
    __shared__ float xsum[2][4];

    int bid = blockIdx.x, t = threadIdx.x;
    int h = t >> 6, m = t & 63;
    int lane = t & 31, wid = t >> 5;

    for (int idx = t; idx < MSZ * DIM; idx += 128)
        mk[idx >> 7][idx & 127] = Mk[idx];
    __syncthreads();

    ull mk2[64];
#pragma unroll
    for (int j = 0; j < 64; j++)
        mk2[j] = pack2(mk[m][2*j], mk[m][2*j + 1]);

    int qp0 = bid * WT_PAIRS;
    float e0 = Ek[(2*qp0)*DIM + t];
    float e1 = Ek[(2*qp0 + 1)*DIM + t];
    int pb = 0;
    for (int i = 0; i < WT_PAIRS; i++) {
        ek[pb][0][t] = e0;
        ek[pb][1][t] = e1;
        __syncthreads();
        if (i + 1 < WT_PAIRS) {
            e0 = Ek[(2*(qp0 + i + 1))*DIM + t];
            e1 = Ek[(2*(qp0 + i + 1) + 1)*DIM + t];
        }
        const ull* ep = (const ull*)ek[pb][h];
        ull a0 = 0ULL, a1 = 0ULL;
#pragma unroll
        for (int j = 0; j < 64; j += 2) {
            a0 = fma2(ep[j],   mk2[j],   a0);
            a1 = fma2(ep[j+1], mk2[j+1], a1);
        }
        float2 ac = unpack2(add2(a0, a1));
        float lv = ac.x + ac.y;

        float wm = lv;
#pragma unroll
        for (int o = 16; o > 0; o >>= 1)
            wm = fmaxf(wm, __shfl_xor_sync(0xffffffffu, wm, o));
        if (lane == 0) xmax[pb][wid] = wm;
        __syncthreads();
        float mx = fmaxf(xmax[pb][h*2], xmax[pb][h*2 + 1]);
        float ev = __expf(lv - mx);
        float ws = ev;
#pragma unroll
        for (int o = 16; o > 0; o >>= 1)
            ws += __shfl_xor_sync(0xffffffffu, ws, o);
        if (lane == 0) xsum[pb][wid] = ws;
        __syncthreads();
        float s = xsum[pb][h*2] + xsum[pb][h*2 + 1];
        g_w[(2*(qp0 + i) + h)*MSZ + m] = __fdividef(ev, s);
        pb ^= 1;
    }
}

// ======================================================================
// Kernel 1b: column-GEMM tables, 250 blocks x 20 rows (2 rows/iter).
// ======================================================================
__global__ void __launch_bounds__(128) k_cgemm(
        const float* __restrict__ Ek, const float* __restrict__ Ev,
        const float* __restrict__ We, const float* __restrict__ be,
        const float* __restrict__ Wa, const float* __restrict__ ba,
        const float* __restrict__ Wf, const float* __restrict__ bf) {
    __shared__ __align__(16) float sv[2][DIM];
    int cb = blockIdx.x, t = threadIdx.x;
    const float *W, *bias, *rows;
    float* outp;
    int mode, row0;
    if (cb < 100)      { W = We;           bias = be; rows = Ev; outp = g_ne; mode = 0; row0 = cb*20; }
    else if (cb < 200) { W = Wa;           bias = ba; rows = Ev; outp = g_a;  mode = 1; row0 = (cb-100)*20; }
    else               { W = Wf + DIM*DIM; bias = bf; rows = Ek; outp = g_fk; mode = 2; row0 = (cb-200)*20; }

    ull w2[64];
#pragma unroll
    for (int j = 0; j < 64; j++)
        w2[j] = pack2(W[(2*j)*DIM + t], W[(2*j+1)*DIM + t]);
    float bv = bias[t];

    float nA = rows[row0*DIM + t];
    float nB = rows[(row0 + 1)*DIM + t];
    for (int i = 0; i < 10; i++) {
        sv[0][t] = nA;
        sv[1][t] = nB;
        __syncthreads();
        if (i < 9) {
            nA = rows[(row0 + 2*i + 2)*DIM + t];
            nB = rows[(row0 + 2*i + 3)*DIM + t];
        }
        const ull* sa = (const ull*)sv[0];
        const ull* sb = (const ull*)sv[1];
        ull aA0 = pack2(bv, 0.f), aA1 = 0ULL;
        ull aB0 = pack2(bv, 0.f), aB1 = 0ULL;
#pragma unroll
        for (int j = 0; j < 64; j += 2) {
            aA0 = fma2(sa[j],   w2[j],   aA0);
            aA1 = fma2(sa[j+1], w2[j+1], aA1);
            aB0 = fma2(sb[j],   w2[j],   aB0);
            aB1 = fma2(sb[j+1], w2[j+1], aB1);
        }
        float2 fA = unpack2(add2(aA0, aA1));
        float2 fB = unpack2(add2(aB0, aB1));
        float gA = fA.x + fA.y, gB = fB.x + fB.y;
        float oA, oB;
        if (mode == 0)      { oA = -sigmoid_fast(gA); oB = -sigmoid_fast(gB); }
        else if (mode == 1) { oA = tanh_fast(gA);     oB = tanh_fast(gB); }
        else                { oA = gA;                oB = gB; }
        outp[(row0 + 2*i)*DIM + t]     = oA;
        outp[(row0 + 2*i + 1)*DIM + t] = oB;
        __syncthreads();
    }
}

// ======================================================================
// Kernel 2: sequential scan, 2 warps/SMSP for latency hiding.
// grid 128 = (batch, half); block 256 = 8 warps x 8 cols.
// lane = me*4 + cp : me = m-eighth (8 m each), cp = col-pair.
// mv[8]/thread; read-reduction = 3 ull shfl_xor; no bars in loop.
// ======================================================================
struct SD { float w[8]; ull ne2, a2; };

__device__ __forceinline__ void sd_load(SD& s, const int2* __restrict__ sidx,
                                        int l, int me, int eoff) {
    int lc = (l < LL) ? l : (LL - 1);
    int2 ix = sidx[lc];
    const float4* wp = (const float4*)(g_w + ix.x + me*8);
    float4 w0 = wp[0], w1 = wp[1];
    s.w[0]=w0.x; s.w[1]=w0.y; s.w[2]=w0.z; s.w[3]=w0.w;
    s.w[4]=w1.x; s.w[5]=w1.y; s.w[6]=w1.z; s.w[7]=w1.w;
    s.ne2 = *(const ull*)(g_ne + ix.y + eoff);
    s.a2  = *(const ull*)(g_a  + ix.y + eoff);
}

__device__ __forceinline__ void scan_step(const SD& s, ull mv[8], int l,
                                          int me, float* rbase) {
    ull r0 = 0ULL, r1 = 0ULL;
#pragma unroll
    for (int j = 0; j < 8; j++) {
        ull w2 = pack2(s.w[j], s.w[j]);
        ull tt = fma2(mv[j], s.ne2, s.a2);        // t = a - mv*e   (ne = -e)
        if (j & 1) r1 = fma2(w2, mv[j], r1);      // read += w * mv_old
        else       r0 = fma2(w2, mv[j], r0);
        mv[j] = fma2(w2, tt, mv[j]);              // mv += w * t
    }
    ull racc = add2(r0, r1);
    racc = add2(racc, __shfl_xor_sync(0xffffffffu, racc, 4));
    racc = add2(racc, __shfl_xor_sync(0xffffffffu, racc, 8));
    racc = add2(racc, __shfl_xor_sync(0xffffffffu, racc, 16));
    if (me == 0) *(ull*)(rbase + l*DIM) = racc;
}

__global__ void __launch_bounds__(256, 1) k_scan(const float* __restrict__ Mv0,
                                                 const int* __restrict__ q,
                                                 const int* __restrict__ r) {
    __shared__ int2 sidx[LL];
    int bx = blockIdx.x, b = bx >> 1, h = bx & 1;
    int tid = threadIdx.x, wid = tid >> 5, lane = tid & 31;
    int me = lane >> 2, cp = lane & 3;

    for (int i = tid; i < LL; i += 256) {
        int qv = q[b*LL + i], rv = r[b*LL + i];
        sidx[i] = make_int2(qv*MSZ, (qv + NUM_C*rv)*DIM);
    }

    int eoff = h*64 + wid*8 + cp*2;
    ull mv[8];
#pragma unroll
    for (int j = 0; j < 8; j++)
        mv[j] = *(const ull*)(Mv0 + (me*8 + j)*DIM + eoff);
    __syncthreads();   // sidx ready; only bar in the kernel

    float* rb = g_read + (b*LL)*DIM + eoff;

    SD A0, A1, B0, B1;
    sd_load(A0, sidx, 0, me, eoff);
    sd_load(A1, sidx, 1, me, eoff);
    sd_load(B0, sidx, 2, me, eoff);
    sd_load(B1, sidx, 3, me, eoff);

    for (int l = 0; l < LL; l += 4) {
        scan_step(A0, mv, l+0, me, rb);
        scan_step(A1, mv, l+1, me, rb);
        sd_load(A0, sidx, l+4, me, eoff);
        sd_load(A1, sidx, l+5, me, eoff);
        scan_step(B0, mv, l+2, me, rb);
        scan_step(B1, mv, l+3, me, rb);
        sd_load(B0, sidx, l+6, me, eoff);
        sd_load(B1, sidx, l+7, me, eoff);
    }
}

// ======================================================================
// Kernel 3: f = tanh(read@Wf_r + fk), p = sigmoid(f.Wp + bp).
// thread = (i-quarter iq, p-pair po): 4 outputs/thread -> 1 LDS.128 : 4 FFMA2.
// 4 tokens/iter; epilogue: warp iq finalizes token iq. 2 bars/iter.
// ======================================================================
__global__ void __launch_bounds__(128, 2) k_fp(const int* __restrict__ q,
                                               const float* __restrict__ Wf,
                                               const float* __restrict__ Wp,
                                               const float* __restrict__ bp,
                                               float* __restrict__ out) {
    __shared__ __align__(16) ull rr[2][4][DIM];      // [pb][token][i] (dup)
    __shared__ __align__(16) ull part[2][4][4][32][2]; // [pb][tok][iq][po][A/B]
    int tid = threadIdx.x;
    int iq = tid >> 5, po = tid & 31;

    ull wfA[32], wfB[32];
#pragma unroll
    for (int i = 0; i < 32; i++) {
        wfA[i] = *(const ull*)(Wf + (iq*32 + i)*DIM + 2*po);
        wfB[i] = *(const ull*)(Wf + (iq*32 + i)*DIM + 64 + 2*po);
    }
    float wp0 = Wp[2*po], wp1 = Wp[2*po + 1];
    float wp2 = Wp[64 + 2*po], wp3 = Wp[64 + 2*po + 1];
    float bpv = bp[0];

    const int stride = gridDim.x * 4;
    int tok0 = blockIdx.x * 4;

    float rv[4];
    ull fkA = 0ULL, fkB = 0ULL;
    if (tok0 < NTOK) {
#pragma unroll
        for (int tt = 0; tt < 4; tt++)
            rv[tt] = g_read[(tok0 + tt)*DIM + tid];
        int qv = q[tok0 + iq];
        fkA = *(const ull*)(g_fk + qv*DIM + 2*po);
        fkB = *(const ull*)(g_fk + qv*DIM + 64 + 2*po);
    }

    int pb = 0;
    for (; tok0 < NTOK; tok0 += stride) {
#pragma unroll
        for (int tt = 0; tt < 4; tt++)
            rr[pb][tt][tid] = pack2(rv[tt], rv[tt]);
        __syncthreads();                               // A

        // prefetch next iteration under the FMA burst
        int tokn = tok0 + stride;
        float rvn[4] = {0.f, 0.f, 0.f, 0.f};
        ull fkAn = 0ULL, fkBn = 0ULL;
        if (tokn < NTOK) {
#pragma unroll
            for (int tt = 0; tt < 4; tt++)
                rvn[tt] = g_read[(tokn + tt)*DIM + tid];
            int qn = q[tokn + iq];
            fkAn = *(const ull*)(g_fk + qn*DIM + 2*po);
            fkBn = *(const ull*)(g_fk + qn*DIM + 64 + 2*po);
        }

        ull aA0[4], aA1[4], aB0[4], aB1[4];
#pragma unroll
        for (int tt = 0; tt < 4; tt++) { aA0[tt]=0ULL; aA1[tt]=0ULL; aB0[tt]=0ULL; aB1[tt]=0ULL; }
#pragma unroll
        for (int j = 0; j < 16; j++) {
#pragma unroll
            for (int tt = 0; tt < 4; tt++) {
                ulonglong2 v = ((const ulonglong2*)&rr[pb][tt][iq*32])[j];
                aA0[tt] = fma2(wfA[2*j],     v.x, aA0[tt]);
                aB0[tt] = fma2(wfB[2*j],     v.x, aB0[tt]);
                aA1[tt] = fma2(wfA[2*j + 1], v.y, aA1[tt]);
                aB1[tt] = fma2(wfB[2*j + 1], v.y, aB1[tt]);
            }
        }
#pragma unroll
        for (int tt = 0; tt < 4; tt++) {
            ulonglong2 pr;
            pr.x = add2(aA0[tt], aA1[tt]);
            pr.y = add2(aB0[tt], aB1[tt]);
            *(ulonglong2*)&part[pb][tt][iq][po][0] = pr;
        }
        __syncthreads();                               // B

        // epilogue: warp iq finalizes token iq
        {
            int tt = iq;
            ull sA = fkA, sB = fkB;
#pragma unroll
            for (int g = 0; g < 4; g++) {
                ulonglong2 pr = *(const ulonglong2*)&part[pb][tt][g][po][0];
                sA = add2(sA, pr.x);
                sB = add2(sB, pr.y);
            }
            float2 fA = unpack2(sA), fB = unpack2(sB);
            float pv = fmaf(tanh_fast(fA.x), wp0,
                       fmaf(tanh_fast(fA.y), wp1,
                       fmaf(tanh_fast(fB.x), wp2, tanh_fast(fB.y) * wp3)));
#pragma unroll
            for (int o = 16; o > 0; o >>= 1)
                pv += __shfl_xor_sync(0xffffffffu, pv, o);
            if (po == 0) out[tok0 + tt] = sigmoid_fast(pv + bpv);
        }

        pb ^= 1;
#pragma unroll
        for (int tt = 0; tt < 4; tt++) rv[tt] = rvn[tt];
        fkA = fkAn; fkB = fkBn;
    }
}

// ---------------- launch ----------------
extern "C" void kernel_launch(void* const* d_in, const int* in_sizes, int n_in,
                              void* d_out, int out_size) {
    const int*   q   = (const int*)d_in[0];
    const int*   r   = (const int*)d_in[1];
    const float* Ek  = (const float*)d_in[2];
    const float* Ev  = (const float*)d_in[3];
    const float* Mk  = (const float*)d_in[4];
    const float* Mv0 = (const float*)d_in[5];
    const float* We  = (const float*)d_in[6];
    const float* be  = (const float*)d_in[7];
    const float* Wa  = (const float*)d_in[8];
    const float* ba  = (const float*)d_in[9];
    const float* Wf  = (const float*)d_in[10];
    const float* bf  = (const float*)d_in[11];
    const float* Wp  = (const float*)d_in[12];
    const float* bp  = (const float*)d_in[13];
    float* out = (float*)d_out;

    k_wtab<<<WT_BLOCKS, 128>>>(Ek, Mk);
    k_cgemm<<<250, 128>>>(Ek, Ev, We, be, Wa, ba, Wf, bf);
    k_scan<<<2*BB, 256>>>(Mv0, q, r);
    k_fp<<<296, 128>>>(q, Wf, Wp, bp, out);
}

// round 6
// speedup vs baseline: 1.6936x; 1.6936x over previous
#include <cuda_runtime.h>

// Inputs: q, r, Ek, Ev, Mk, Mv0, We, be, Wa, ba, Wf, bf, Wp, bp
// q,r int32 [64,512]; rest float32. Output: p [64,512] float32.

#define NUM_C 1000
#define DIM   128
#define MSZ   64
#define BB    64
#define LL    512
#define NTOK  (BB*LL)

typedef unsigned long long ull;

// ---------------- device scratch ----------------
__device__ float g_w  [NUM_C*MSZ];     // softmax(Ek[q] @ Mk^T)          [1000,64]
__device__ float g_ne [2*NUM_C*DIM];   // -sigmoid(Ev@We+be)  (negated!) [2000,128]
__device__ float g_a  [2*NUM_C*DIM];   // tanh(Ev@Wa+ba)                 [2000,128]
__device__ float g_fk [NUM_C*DIM];     // Ek@Wf[128:256] + bf            [1000,128]
__device__ float g_read[NTOK*DIM];     // scan output                    [B*L,128]

// ---------------- f32x2 helpers ----------------
__device__ __forceinline__ ull fma2(ull a, ull b, ull c) {
    ull d; asm("fma.rn.f32x2 %0, %1, %2, %3;" : "=l"(d) : "l"(a), "l"(b), "l"(c)); return d;
}
__device__ __forceinline__ ull add2(ull a, ull b) {
    ull d; asm("add.rn.f32x2 %0, %1, %2;" : "=l"(d) : "l"(a), "l"(b)); return d;
}
__device__ __forceinline__ ull pack2(float x, float y) {
    ull d; asm("mov.b64 %0, {%1, %2};" : "=l"(d) : "f"(x), "f"(y)); return d;
}
__device__ __forceinline__ float2 unpack2(ull v) {
    float2 r; asm("mov.b64 {%0, %1}, %2;" : "=f"(r.x), "=f"(r.y) : "l"(v)); return r;
}
__device__ __forceinline__ float sigmoid_fast(float x) {
    return __fdividef(1.0f, 1.0f + __expf(-x));
}
__device__ __forceinline__ float tanh_fast(float x) {
    return 1.0f - __fdividef(2.0f, __expf(2.0f * x) + 1.0f);
}

// ======================================================================
// Kernel 1a: softmax correlation-weight table. 50 blocks x 10 q-pairs.
// ======================================================================
#define WT_BLOCKS 50
#define WT_PAIRS  10

__global__ void __launch_bounds__(128) k_wtab(const float* __restrict__ Ek,
                                              const float* __restrict__ Mk) {
    __shared__ float mk[MSZ][DIM + 2];
    __shared__ float ek[2][2][DIM];
    __shared__ float xmax[2][4];
    __shared__ float xsum[2][4];

    int bid = blockIdx.x, t = threadIdx.x;
    int h = t >> 6, m = t & 63;
    int lane = t & 31, wid = t >> 5;

    for (int idx = t; idx < MSZ * DIM; idx += 128)
        mk[idx >> 7][idx & 127] = Mk[idx];
    __syncthreads();

    ull mk2[64];
#pragma unroll
    for (int j = 0; j < 64; j++)
        mk2[j] = pack2(mk[m][2*j], mk[m][2*j + 1]);

    int qp0 = bid * WT_PAIRS;
    float e0 = Ek[(2*qp0)*DIM + t];
    float e1 = Ek[(2*qp0 + 1)*DIM + t];
    int pb = 0;
    for (int i = 0; i < WT_PAIRS; i++) {
        ek[pb][0][t] = e0;
        ek[pb][1][t] = e1;
        __syncthreads();
        if (i + 1 < WT_PAIRS) {
            e0 = Ek[(2*(qp0 + i + 1))*DIM + t];
            e1 = Ek[(2*(qp0 + i + 1) + 1)*DIM + t];
        }
        const ull* ep = (const ull*)ek[pb][h];
        ull a0 = 0ULL, a1 = 0ULL;
#pragma unroll
        for (int j = 0; j < 64; j += 2) {
            a0 = fma2(ep[j],   mk2[j],   a0);
            a1 = fma2(ep[j+1], mk2[j+1], a1);
        }
        float2 ac = unpack2(add2(a0, a1));
        float lv = ac.x + ac.y;

        float wm = lv;
#pragma unroll
        for (int o = 16; o > 0; o >>= 1)
            wm = fmaxf(wm, __shfl_xor_sync(0xffffffffu, wm, o));
        if (lane == 0) xmax[pb][wid] = wm;
        __syncthreads();
        float mx = fmaxf(xmax[pb][h*2], xmax[pb][h*2 + 1]);
        float ev = __expf(lv - mx);
        float ws = ev;
#pragma unroll
        for (int o = 16; o > 0; o >>= 1)
            ws += __shfl_xor_sync(0xffffffffu, ws, o);
        if (lane == 0) xsum[pb][wid] = ws;
        __syncthreads();
        float s = xsum[pb][h*2] + xsum[pb][h*2 + 1];
        g_w[(2*(qp0 + i) + h)*MSZ + m] = __fdividef(ev, s);
        pb ^= 1;
    }
}

// ======================================================================
// Kernel 1b: column-GEMM tables, 250 blocks x 20 rows (2 rows/iter).
// ======================================================================
__global__ void __launch_bounds__(128) k_cgemm(
        const float* __restrict__ Ek, const float* __restrict__ Ev,
        const float* __restrict__ We, const float* __restrict__ be,
        const float* __restrict__ Wa, const float* __restrict__ ba,
        const float* __restrict__ Wf, const float* __restrict__ bf) {
    __shared__ __align__(16) float sv[2][DIM];
    int cb = blockIdx.x, t = threadIdx.x;
    const float *W, *bias, *rows;
    float* outp;
    int mode, row0;
    if (cb < 100)      { W = We;           bias = be; rows = Ev; outp = g_ne; mode = 0; row0 = cb*20; }
    else if (cb < 200) { W = Wa;           bias = ba; rows = Ev; outp = g_a;  mode = 1; row0 = (cb-100)*20; }
    else               { W = Wf + DIM*DIM; bias = bf; rows = Ek; outp = g_fk; mode = 2; row0 = (cb-200)*20; }

    ull w2[64];
#pragma unroll
    for (int j = 0; j < 64; j++)
        w2[j] = pack2(W[(2*j)*DIM + t], W[(2*j+1)*DIM + t]);
    float bv = bias[t];

    float nA = rows[row0*DIM + t];
    float nB = rows[(row0 + 1)*DIM + t];
    for (int i = 0; i < 10; i++) {
        sv[0][t] = nA;
        sv[1][t] = nB;
        __syncthreads();
        if (i < 9) {
            nA = rows[(row0 + 2*i + 2)*DIM + t];
            nB = rows[(row0 + 2*i + 3)*DIM + t];
        }
        const ull* sa = (const ull*)sv[0];
        const ull* sb = (const ull*)sv[1];
        ull aA0 = pack2(bv, 0.f), aA1 = 0ULL;
        ull aB0 = pack2(bv, 0.f), aB1 = 0ULL;
#pragma unroll
        for (int j = 0; j < 64; j += 2) {
            aA0 = fma2(sa[j],   w2[j],   aA0);
            aA1 = fma2(sa[j+1], w2[j+1], aA1);
            aB0 = fma2(sb[j],   w2[j],   aB0);
            aB1 = fma2(sb[j+1], w2[j+1], aB1);
        }
        float2 fA = unpack2(add2(aA0, aA1));
        float2 fB = unpack2(add2(aB0, aB1));
        float gA = fA.x + fA.y, gB = fB.x + fB.y;
        float oA, oB;
        if (mode == 0)      { oA = -sigmoid_fast(gA); oB = -sigmoid_fast(gB); }
        else if (mode == 1) { oA = tanh_fast(gA);     oB = tanh_fast(gB); }
        else                { oA = gA;                oB = gB; }
        outp[(row0 + 2*i)*DIM + t]     = oA;
        outp[(row0 + 2*i + 1)*DIM + t] = oB;
        __syncthreads();
    }
}

// ======================================================================
// Kernel 2: barrier-free scan, pipeline depth 8.
// grid 128 = (batch, half); block 128 = 4 warps x 16 cols.
// lane = mq*8 + cpi (mq = m-quarter, cpi = col-pair); mv[16]/thread.
// Reduction: 2 ull shfl_xor (strides 8,16). Loads issued 8 steps ahead.
// ======================================================================
struct SD { float w[16]; ull ne2, a2; };

__device__ __forceinline__ void sd_load(SD& s, const int2* __restrict__ sidx,
                                        int l, int mq, int eoff) {
    int lc = (l < LL) ? l : (LL - 1);
    int2 ix = sidx[lc];
    const float4* wp = (const float4*)(g_w + ix.x + mq*16);
    float4 w0 = wp[0], w1 = wp[1], w2 = wp[2], w3 = wp[3];
    s.w[0]=w0.x; s.w[1]=w0.y; s.w[2]=w0.z; s.w[3]=w0.w;
    s.w[4]=w1.x; s.w[5]=w1.y; s.w[6]=w1.z; s.w[7]=w1.w;
    s.w[8]=w2.x; s.w[9]=w2.y; s.w[10]=w2.z; s.w[11]=w2.w;
    s.w[12]=w3.x; s.w[13]=w3.y; s.w[14]=w3.z; s.w[15]=w3.w;
    s.ne2 = *(const ull*)(g_ne + ix.y + eoff);
    s.a2  = *(const ull*)(g_a  + ix.y + eoff);
}

__device__ __forceinline__ void scan_step(const SD& s, ull mv[16], int l,
                                          int mq, float* rbase) {
    ull r0 = 0ULL, r1 = 0ULL;
#pragma unroll
    for (int j = 0; j < 16; j++) {
        ull w2 = pack2(s.w[j], s.w[j]);
        ull tt = fma2(mv[j], s.ne2, s.a2);        // t = a - mv*e   (ne = -e)
        if (j & 1) r1 = fma2(w2, mv[j], r1);      // read += w * mv_old
        else       r0 = fma2(w2, mv[j], r0);
        mv[j] = fma2(w2, tt, mv[j]);              // mv += w * t
    }
    ull racc = add2(r0, r1);
    racc = add2(racc, __shfl_xor_sync(0xffffffffu, racc, 8));
    racc = add2(racc, __shfl_xor_sync(0xffffffffu, racc, 16));
    if (mq == 0) *(ull*)(rbase + l*DIM) = racc;
}

__global__ void __launch_bounds__(128, 1) k_scan(const float* __restrict__ Mv0,
                                                 const int* __restrict__ q,
                                                 const int* __restrict__ r) {
    __shared__ int2 sidx[LL];
    int bx = blockIdx.x, b = bx >> 1, h = bx & 1;
    int tid = threadIdx.x, wid = tid >> 5, lane = tid & 31;
    int mq = lane >> 3, cpi = lane & 7;

    for (int i = tid; i < LL; i += 128) {
        int qv = q[b*LL + i], rv = r[b*LL + i];
        sidx[i] = make_int2(qv*MSZ, (qv + NUM_C*rv)*DIM);
    }

    int eoff = h*64 + wid*16 + cpi*2;
    ull mv[16];
#pragma unroll
    for (int j = 0; j < 16; j++)
        mv[j] = *(const ull*)(Mv0 + (mq*16 + j)*DIM + eoff);
    __syncthreads();   // sidx ready; only bar in the kernel

    float* rb = g_read + (b*LL)*DIM + eoff;

    SD S[8];
#pragma unroll
    for (int i = 0; i < 8; i++) sd_load(S[i], sidx, i, mq, eoff);

    for (int l = 0; l < LL; l += 8) {
#pragma unroll
        for (int u = 0; u < 8; u++) {
            scan_step(S[u], mv, l + u, mq, rb);
            sd_load(S[u], sidx, l + u + 8, mq, eoff);   // distance-8 prefetch
        }
    }
}

// ======================================================================
// Kernel 3: f = tanh(read@Wf_r + fk), p = sigmoid(f.Wp + bp).
// 8 tokens/iter; thread = (i-half g, p-pair p) with wf[64] in regs.
// Both halves write partials; epilogue = warp w finalizes tokens 2w,2w+1.
// q/fk/read prefetched one full iteration ahead.
// ======================================================================
__global__ void __launch_bounds__(128, 2) k_fp(const int* __restrict__ q,
                                               const float* __restrict__ Wf,
                                               const float* __restrict__ Wp,
                                               const float* __restrict__ bp,
                                               float* __restrict__ out) {
    __shared__ __align__(16) ull rr[2][8][DIM];       // [pb][token][dim] (dup)   16KB
    __shared__ __align__(16) ull part[2][8][2][64];   // [pb][token][half][p]     16KB
    int tid = threadIdx.x;
    int g = tid >> 6, p = tid & 63;
    int wid = tid >> 5, lane = tid & 31;

    ull wf[64];
#pragma unroll
    for (int j = 0; j < 64; j++)
        wf[j] = *(const ull*)(Wf + (g*64 + j)*DIM + 2*p);
    // epilogue weights: lane owns output pairs (lane) and (lane+32)
    float wp0 = Wp[2*lane],      wp1 = Wp[2*lane + 1];
    float wp2 = Wp[2*lane + 64], wp3 = Wp[2*lane + 65];
    float bpv = bp[0];

    const int stride = gridDim.x * 8;
    int tok0 = blockIdx.x * 8;

    // iteration-ahead pipeline state
    float rv[8];
    ull fkA0 = 0ULL, fkA1 = 0ULL, fkB0 = 0ULL, fkB1 = 0ULL;  // warp's 2 tokens
    if (tok0 < NTOK) {
#pragma unroll
        for (int tt = 0; tt < 8; tt++)
            rv[tt] = g_read[(tok0 + tt)*DIM + tid];
        int q0 = q[tok0 + 2*wid],  q1 = q[tok0 + 2*wid + 1];
        fkA0 = *(const ull*)(g_fk + q0*DIM + 2*lane);
        fkA1 = *(const ull*)(g_fk + q0*DIM + 2*lane + 64);
        fkB0 = *(const ull*)(g_fk + q1*DIM + 2*lane);
        fkB1 = *(const ull*)(g_fk + q1*DIM + 2*lane + 64);
    }

    int pb = 0;
    for (; tok0 < NTOK; tok0 += stride) {
#pragma unroll
        for (int tt = 0; tt < 8; tt++)
            rr[pb][tt][tid] = pack2(rv[tt], rv[tt]);
        __syncthreads();                               // A

        // prefetch next iteration (hidden under the 512-FFMA2 burst)
        int tokn = tok0 + stride;
        float rvn[8];
        ull fkA0n = 0ULL, fkA1n = 0ULL, fkB0n = 0ULL, fkB1n = 0ULL;
        if (tokn < NTOK) {
#pragma unroll
            for (int tt = 0; tt < 8; tt++)
                rvn[tt] = g_read[(tokn + tt)*DIM + tid];
            int qn0 = q[tokn + 2*wid], qn1 = q[tokn + 2*wid + 1];
            fkA0n = *(const ull*)(g_fk + qn0*DIM + 2*lane);
            fkA1n = *(const ull*)(g_fk + qn0*DIM + 2*lane + 64);
            fkB0n = *(const ull*)(g_fk + qn1*DIM + 2*lane);
            fkB1n = *(const ull*)(g_fk + qn1*DIM + 2*lane + 64);
        } else {
#pragma unroll
            for (int tt = 0; tt < 8; tt++) rvn[tt] = 0.f;
        }

        // GEMV: 8 tokens, half-input per thread, output pair p
        ull acc0[8], acc1[8];
#pragma unroll
        for (int tt = 0; tt < 8; tt++) { acc0[tt] = 0ULL; acc1[tt] = 0ULL; }
#pragma unroll
        for (int j = 0; j < 32; j++) {
#pragma unroll
            for (int tt = 0; tt < 8; tt++) {
                ulonglong2 v = ((const ulonglong2*)&rr[pb][tt][g*64])[j];
                acc0[tt] = fma2(wf[2*j],     v.x, acc0[tt]);
                acc1[tt] = fma2(wf[2*j + 1], v.y, acc1[tt]);
            }
        }
#pragma unroll
        for (int tt = 0; tt < 8; tt++)
            part[pb][tt][g][p] = add2(acc0[tt], acc1[tt]);
        __syncthreads();                               // B

        // epilogue: warp wid finalizes tokens 2*wid, 2*wid+1
        {
            int t0 = 2*wid, t1 = t0 + 1;
            ull sA0 = add2(add2(part[pb][t0][0][lane],      part[pb][t0][1][lane]),      fkA0);
            ull sA1 = add2(add2(part[pb][t0][0][lane + 32], part[pb][t0][1][lane + 32]), fkA1);
            ull sB0 = add2(add2(part[pb][t1][0][lane],      part[pb][t1][1][lane]),      fkB0);
            ull sB1 = add2(add2(part[pb][t1][0][lane + 32], part[pb][t1][1][lane + 32]), fkB1);
            float2 a0 = unpack2(sA0), a1 = unpack2(sA1);
            float2 b0 = unpack2(sB0), b1 = unpack2(sB1);
            float pvA = fmaf(tanh_fast(a0.x), wp0,
                        fmaf(tanh_fast(a0.y), wp1,
                        fmaf(tanh_fast(a1.x), wp2, tanh_fast(a1.y) * wp3)));
            float pvB = fmaf(tanh_fast(b0.x), wp0,
                        fmaf(tanh_fast(b0.y), wp1,
                        fmaf(tanh_fast(b1.x), wp2, tanh_fast(b1.y) * wp3)));
#pragma unroll
            for (int o = 16; o > 0; o >>= 1) {
                pvA += __shfl_xor_sync(0xffffffffu, pvA, o);
                pvB += __shfl_xor_sync(0xffffffffu, pvB, o);
            }
            if (lane == 0) {
                out[tok0 + t0] = sigmoid_fast(pvA + bpv);
                out[tok0 + t1] = sigmoid_fast(pvB + bpv);
            }
        }

        pb ^= 1;
#pragma unroll
        for (int tt = 0; tt < 8; tt++) rv[tt] = rvn[tt];
        fkA0 = fkA0n; fkA1 = fkA1n; fkB0 = fkB0n; fkB1 = fkB1n;
    }
}

// ---------------- launch ----------------
extern "C" void kernel_launch(void* const* d_in, const int* in_sizes, int n_in,
                              void* d_out, int out_size) {
    const int*   q   = (const int*)d_in[0];
    const int*   r   = (const int*)d_in[1];
    const float* Ek  = (const float*)d_in[2];
    const float* Ev  = (const float*)d_in[3];
    const float* Mk  = (const float*)d_in[4];
    const float* Mv0 = (const float*)d_in[5];
    const float* We  = (const float*)d_in[6];
    const float* be  = (const float*)d_in[7];
    const float* Wa  = (const float*)d_in[8];
    const float* ba  = (const float*)d_in[9];
    const float* Wf  = (const float*)d_in[10];
    const float* bf  = (const float*)d_in[11];
    const float* Wp  = (const float*)d_in[12];
    const float* bp  = (const float*)d_in[13];
    float* out = (float*)d_out;

    k_wtab<<<WT_BLOCKS, 128>>>(Ek, Mk);
    k_cgemm<<<250, 128>>>(Ek, Ev, We, be, Wa, ba, Wf, bf);
    k_scan<<<2*BB, 128>>>(Mv0, q, r);
    k_fp<<<296, 128>>>(q, Wf, Wp, bp, out);
}